// round 17
// baseline (speedup 1.0000x reference)
#include <cuda_runtime.h>
#include <cuda_bf16.h>

// MTCNN generate-boxes + greedy NMS, H=W=96, STRIDE=2, CELL=12, SCALE=0.6,
// THR_SCORE=0.6, THR_NMS=0.5.
//
// Exact structure (validated R12/R13): x1(c)=round(10c/3)=(10c+1)/3, x2=x1+20,
// all boxes 21x21; IoU>0.5 <=> (21-|dx|)(21-|dy|) > 294; suppression confined
// to a 12-neighbor stencil whose overlap pattern is PERIOD-3 in r and c:
//   (0,+-1),(+-1,0): always overlap
//   (0,+2): only c%3==2   (0,-2): only c%3==1   (rows analogous)
//   (+1,+1): except r%3==1&&c%3==1   (+1,-1): except r%3==1&&c%3==2
//   (-1,-1): except r%3==2&&c%3==2   (-1,+1): except r%3==2&&c%3==1
//
// Priority (score desc, idx asc) is a strict total order => only 6 raw
// comparison bitmaps needed (ballot-built); opposite offsets are shifted
// complements. Greedy NMS = lex-first MIS of this static DAG, computed as a
// monotone fixpoint on (K=kept, A=alive) bitmaps. Both maps move one
// direction per bit and every observed transition is truth-based, so the
// iteration is correct under arbitrary interleaving -> multiple in-place
// sub-steps between barriers.

#define HH 96
#define WW 96
#define NN (HH * WW)
#define PITCH 97
#define NTH 384
#define NWORDS 288
#define SUBS 3

__device__ __forceinline__ uint2 lds_v2_vol(const uint2* p) {
    uint2 v;
    unsigned a = (unsigned)__cvta_generic_to_shared((void*)p);
    asm volatile("ld.volatile.shared.v2.u32 {%0,%1}, [%2];"
                 : "=r"(v.x), "=r"(v.y) : "r"(a));
    return v;
}
__device__ __forceinline__ void sts_v2_vol(uint2* p, unsigned x, unsigned y) {
    unsigned a = (unsigned)__cvta_generic_to_shared((void*)p);
    asm volatile("st.volatile.shared.v2.u32 [%0], {%1,%2};"
                 :: "r"(a), "r"(x), "r"(y) : "memory");
}

// bits b with (32*wi + b) % 3 == p
__device__ __forceinline__ unsigned colmask(int wi, int p) {
    const unsigned M[3] = {0x49249249u, 0x92492492u, 0x24924924u};
    return M[((p - 2 * wi) % 3 + 3) % 3];
}

__global__ void __launch_bounds__(NTH, 1)
mtcnn_nms_kernel(const float* __restrict__ cls,
                 const float* __restrict__ reg,
                 float* __restrict__ out)
{
    __shared__ float    sc[HH * PITCH];     // 37248 B padded scores
    __shared__ unsigned hpbm[6][NWORDS];    //  6912 B raw priority bitmaps
    __shared__ uint2    st[NWORDS];         //  2304 B (x=K kept, y=A alive)

    const int tid = threadIdx.x;

    // ---- load cls_prob into padded smem ----
#pragma unroll
    for (int k = 0; k < 6; ++k) {
        const int idx = tid + k * NTH;                 // 2304 float4
        const float4 v = reinterpret_cast<const float4*>(cls)[idx];
        const int rr = (4 * idx) / WW, cc = (4 * idx) % WW;
        float* p = &sc[rr * PITCH + cc];
        p[0] = v.x; p[1] = v.y; p[2] = v.z; p[3] = v.w;
    }
    __syncthreads();

    // ---- ballot phase: valid bitmap + 6 raw priority bitmaps ----
    // base offsets (all have positive linear index delta => tie loses):
    //   0:(0,+1) 1:(0,+2) 2:(+1,0) 3:(+2,0) 4:(+1,+1) 5:(+1,-1)
    {
        const int DRo[6] = {0, 0, 1, 2, 1, 1};
        const int DCo[6] = {1, 2, 0, 0, 1, -1};
#pragma unroll
        for (int k = 0; k < 24; ++k) {
            const int i = tid + k * NTH;               // warps align to words
            const int rr = i / WW, cc = i % WW;
            const float si = sc[rr * PITCH + cc];
            const unsigned vb = __ballot_sync(~0u, si > 0.6f);
            unsigned hp[6];
#pragma unroll
            for (int o = 0; o < 6; ++o) {
                int nr = rr + DRo[o]; nr = nr > 95 ? 95 : nr;
                int nc = cc + DCo[o]; nc = nc < 0 ? 0 : (nc > 95 ? 95 : nc);
                const float sj = sc[nr * PITCH + nc];
                hp[o] = __ballot_sync(~0u, sj > si);   // strict: tie -> lose
            }
            if ((i & 31) == 0) {
                const int w = i >> 5;
#pragma unroll
                for (int o = 0; o < 6; ++o) hpbm[o][w] = hp[o];
                st[w] = make_uint2(0u, vb);
            }
        }
    }
    __syncthreads();

    // ---- build 12 per-offset dominance words (registers, row-owner t<96) ----
    const int r = tid;
    unsigned dm[12][3];
    unsigned kk[3], aa[3];
    if (r < HH) {
        const int rp = r % 3;
#pragma unroll
        for (int wi = 0; wi < 3; ++wi) {
            const unsigned b_cge1  = (wi == 0) ? ~1u : ~0u;
            const unsigned b_cge2  = (wi == 0) ? ~3u : ~0u;
            const unsigned b_cle94 = (wi == 2) ? 0x7fffffffu : ~0u;
            const unsigned b_cle93 = (wi == 2) ? 0x3fffffffu : ~0u;
            const int base = r * 3 + wi;
            const unsigned h0 = hpbm[0][base], h1 = hpbm[1][base],
                           h2 = hpbm[2][base], h3 = hpbm[3][base],
                           h4 = hpbm[4][base], h5 = hpbm[5][base];
            // base offsets
            dm[0][wi] = h0 & b_cle94;                                   // (0,+1)
            dm[1][wi] = h1 & colmask(wi, 2) & b_cle93;                  // (0,+2)
            dm[2][wi] = (r <= 94) ? h2 : 0u;                            // (+1,0)
            dm[3][wi] = (rp == 2 && r <= 93) ? h3 : 0u;                 // (+2,0)
            dm[4][wi] = (r <= 94) ? (h4 & b_cle94 &
                          (rp == 1 ? ~colmask(wi, 1) : ~0u)) : 0u;      // (+1,+1)
            dm[5][wi] = (r <= 94) ? (h5 & b_cge1 &
                          (rp == 1 ? ~colmask(wi, 2) : ~0u)) : 0u;      // (+1,-1)
            // derived (shifted complements)
            {   // (0,-1): ~hp0[r] << 1
                const unsigned lo = (wi > 0) ? ~hpbm[0][base - 1] : 0u;
                dm[6][wi] = __funnelshift_l(lo, ~h0, 1) & b_cge1;
            }
            {   // (0,-2): ~hp1[r] << 2, ovl c%3==1
                const unsigned lo = (wi > 0) ? ~hpbm[1][base - 1] : 0u;
                dm[7][wi] = __funnelshift_l(lo, ~h1, 2) & colmask(wi, 1) & b_cge2;
            }
            dm[8][wi] = (r >= 1) ? ~hpbm[2][base - 3] : 0u;             // (-1,0)
            dm[9][wi] = (rp == 1 && r >= 2) ? ~hpbm[3][base - 6] : 0u;  // (-2,0)
            {   // (-1,-1): ~hp4[r-1] << 1, ovl !(r%3==2 && c%3==2)
                unsigned v = 0u;
                if (r >= 1) {
                    const unsigned lo = (wi > 0) ? ~hpbm[4][base - 4] : 0u;
                    v = __funnelshift_l(lo, ~hpbm[4][base - 3], 1) & b_cge1;
                    if (rp == 2) v &= ~colmask(wi, 2);
                }
                dm[10][wi] = v;
            }
            {   // (-1,+1): ~hp5[r-1] >> 1, ovl !(r%3==2 && c%3==1)
                unsigned v = 0u;
                if (r >= 1) {
                    const unsigned hi = (wi < 2) ? ~hpbm[5][base - 2] : 0u;
                    v = __funnelshift_r(~hpbm[5][base - 3], hi, 1) & b_cle94;
                    if (rp == 2) v &= ~colmask(wi, 1);
                }
                dm[11][wi] = v;
            }
        }
        kk[0] = 0u; kk[1] = 0u; kk[2] = 0u;
        aa[0] = st[r * 3 + 0].y; aa[1] = st[r * 3 + 1].y; aa[2] = st[r * 3 + 2].y;
    }

    // ---- asynchronous monotone fixpoint ----
    const int DR12[12] = {0, 0, 1, 2, 1, 1,  0,  0, -1, -2, -1, -1};
    const int DC12[12] = {1, 2, 0, 0, 1, -1, -1, -2, 0,  0,  -1, 1};

    for (int it = 0; it < 4096; ++it) {
        int ch = 0;
        if (r < HH) {
            const int rm2 = (r >= 2) ? r - 2 : 0;
            const int rm1 = (r >= 1) ? r - 1 : 0;
            const int rp1 = (r <= 94) ? r + 1 : 95;
            const int rp2 = (r <= 93) ? r + 2 : 95;
#pragma unroll
            for (int s = 0; s < SUBS; ++s) {
                unsigned RK[5][3], RA[5][3];
#pragma unroll
                for (int w = 0; w < 3; ++w) {
                    uint2 v0 = lds_v2_vol(&st[rm2 * 3 + w]);
                    uint2 v1 = lds_v2_vol(&st[rm1 * 3 + w]);
                    uint2 v3 = lds_v2_vol(&st[rp1 * 3 + w]);
                    uint2 v4 = lds_v2_vol(&st[rp2 * 3 + w]);
                    RK[0][w] = v0.x; RA[0][w] = v0.y;
                    RK[1][w] = v1.x; RA[1][w] = v1.y;
                    RK[3][w] = v3.x; RA[3][w] = v3.y;
                    RK[4][w] = v4.x; RA[4][w] = v4.y;
                    RK[2][w] = kk[w]; RA[2][w] = aa[w];
                }
#pragma unroll
                for (int wi = 0; wi < 3; ++wi) {
                    const unsigned U = aa[wi] & ~kk[wi];
                    unsigned pend = 0u, kill = 0u;
#pragma unroll
                    for (int o = 0; o < 12; ++o) {
                        const int q = DR12[o] + 2;
                        const int dc = DC12[o];
                        unsigned sA, sK;
                        if (dc == 0)      { sA = RA[q][wi]; sK = RK[q][wi]; }
                        else if (dc == 1) {
                            const unsigned hA = (wi < 2) ? RA[q][wi + 1] : 0u;
                            const unsigned hK = (wi < 2) ? RK[q][wi + 1] : 0u;
                            sA = __funnelshift_r(RA[q][wi], hA, 1);
                            sK = __funnelshift_r(RK[q][wi], hK, 1);
                        } else if (dc == 2) {
                            const unsigned hA = (wi < 2) ? RA[q][wi + 1] : 0u;
                            const unsigned hK = (wi < 2) ? RK[q][wi + 1] : 0u;
                            sA = __funnelshift_r(RA[q][wi], hA, 2);
                            sK = __funnelshift_r(RK[q][wi], hK, 2);
                        } else if (dc == -1) {
                            const unsigned lA = (wi > 0) ? RA[q][wi - 1] : 0u;
                            const unsigned lK = (wi > 0) ? RK[q][wi - 1] : 0u;
                            sA = __funnelshift_l(lA, RA[q][wi], 1);
                            sK = __funnelshift_l(lK, RK[q][wi], 1);
                        } else {
                            const unsigned lA = (wi > 0) ? RA[q][wi - 1] : 0u;
                            const unsigned lK = (wi > 0) ? RK[q][wi - 1] : 0u;
                            sA = __funnelshift_l(lA, RA[q][wi], 2);
                            sK = __funnelshift_l(lK, RK[q][wi], 2);
                        }
                        pend |= sA & dm[o][wi];
                        kill |= sK & dm[o][wi];
                    }
                    const unsigned kept   = U & ~pend;   // no dominating ALIVE
                    const unsigned killed = U & kill;    // dominating KEPT
                    if (kept | killed) {
                        kk[wi] |= kept;
                        aa[wi] &= ~killed;
                        ch = 1;
                    }
                }
                sts_v2_vol(&st[r * 3 + 0], kk[0], aa[0]);
                sts_v2_vol(&st[r * 3 + 1], kk[1], aa[1]);
                sts_v2_vol(&st[r * 3 + 2], kk[2], aa[2]);
            }
        }
        if (__syncthreads_or(ch) == 0) break;
    }

    // ---- output: boxes_c * keep ----
#pragma unroll
    for (int k = 0; k < 24; ++k) {
        const int i = tid + k * NTH;
        const int rr = i / WW, cc = i % WW;
        const float4 rg = reinterpret_cast<const float4*>(reg)[i];
        const unsigned kw = st[i >> 5].x;
        const float m = ((kw >> (i & 31)) & 1u) ? 1.0f : 0.0f;
        const float x1 = (float)((10 * cc + 1) / 3);
        const float y1 = (float)((10 * rr + 1) / 3);
        out[i * 5 + 0] = (x1 + rg.x * 21.0f) * m;
        out[i * 5 + 1] = (y1 + rg.y * 21.0f) * m;
        out[i * 5 + 2] = (x1 + 20.0f + rg.z * 21.0f) * m;
        out[i * 5 + 3] = (y1 + 20.0f + rg.w * 21.0f) * m;
        out[i * 5 + 4] = sc[rr * PITCH + cc] * m;
    }
}

extern "C" void kernel_launch(void* const* d_in, const int* in_sizes, int n_in,
                              void* d_out, int out_size)
{
    const float* cls = (const float*)d_in[0];   // cls_prob  [96,96]
    const float* reg = (const float*)d_in[1];   // bbox_pred [96,96,4]
    float* out = (float*)d_out;                 // [9216, 5]
    (void)in_sizes; (void)n_in; (void)out_size;
    mtcnn_nms_kernel<<<1, NTH>>>(cls, reg, out);
}